// round 1
// baseline (speedup 1.0000x reference)
#include <cuda_runtime.h>
#include <math.h>
#include <stdint.h>

// Problem constants
#define BATCH   4
#define N_DAY   2048
#define N_CELLS 8192
#define D_MICRO 11
#define D       256
#define TOPK    32

#define ROWS_Q  (BATCH * N_DAY)    // 8192
#define ROWS_M  (BATCH * N_CELLS)  // 32768

// ---------------- scratch (__device__ globals, allowed) ----------------
__device__ float g_xmicro[ROWS_Q * D];                     // 8 MB
__device__ float g_q     [ROWS_Q * D];                     // 8 MB
__device__ float g_k     [ROWS_M * D];                     // 32 MB
__device__ float g_v     [ROWS_M * D];                     // 32 MB
__device__ float g_scores[(size_t)BATCH * N_DAY * N_CELLS]; // 256 MB
__device__ float g_ctx   [ROWS_Q * D];                     // 8 MB

// ---------------- micro projection: [8192,11] @ [11,256] + b ----------------
__global__ void __launch_bounds__(256) micro_proj_kernel(
    const float* __restrict__ micro, const float* __restrict__ w,
    const float* __restrict__ b, float* __restrict__ out)
{
    __shared__ float ws[D_MICRO * D];   // 11*256
    __shared__ float bs[D];
    __shared__ float ms[8][D_MICRO];
    int tid = threadIdx.x;
    for (int i = tid; i < D_MICRO * D; i += 256) ws[i] = w[i];
    bs[tid] = b[tid];
    int row0 = blockIdx.x * 8;
    for (int i = tid; i < 8 * D_MICRO; i += 256)
        ms[i / D_MICRO][i % D_MICRO] = micro[(size_t)row0 * D_MICRO + i];
    __syncthreads();
    #pragma unroll
    for (int r = 0; r < 8; r++) {
        float s = bs[tid];
        #pragma unroll
        for (int k = 0; k < D_MICRO; k++) s += ms[r][k] * ws[k * D + tid];
        out[(size_t)(row0 + r) * D + tid] = s;
    }
}

// ---------------- generic fp32 SGEMM: C = A[M,K] @ B[K,N] (+ add + bias) ----------------
#define BM 128
#define BN 128
#define BKK 8

__global__ void __launch_bounds__(256) gemm_nn_kernel(
    const float* __restrict__ A, const float* __restrict__ B,
    float* __restrict__ C, int M, int N, int K,
    const float* __restrict__ addsrc, const float* __restrict__ bias)
{
    __shared__ float As[BKK][BM + 4];
    __shared__ float Bs[BKK][BN + 4];
    int tid = threadIdx.x;
    int bm = blockIdx.y * BM;
    int bn = blockIdx.x * BN;
    int arow = tid >> 1, ak = (tid & 1) * 4;     // A: 128 rows x 8 k
    int brow = tid >> 5, bc = (tid & 31) * 4;    // B: 8 rows x 128 n
    int tx = tid & 15, ty = tid >> 4;
    int tm = ty * 8, tn = tx * 8;

    float acc[8][8];
    #pragma unroll
    for (int i = 0; i < 8; i++)
        #pragma unroll
        for (int j = 0; j < 8; j++) acc[i][j] = 0.f;

    for (int k0 = 0; k0 < K; k0 += BKK) {
        float4 av = *(const float4*)(A + (size_t)(bm + arow) * K + k0 + ak);
        float4 bv = *(const float4*)(B + (size_t)(k0 + brow) * N + bn + bc);
        As[ak + 0][arow] = av.x; As[ak + 1][arow] = av.y;
        As[ak + 2][arow] = av.z; As[ak + 3][arow] = av.w;
        *(float4*)&Bs[brow][bc] = bv;
        __syncthreads();
        #pragma unroll
        for (int k = 0; k < BKK; k++) {
            float a[8], bfr[8];
            #pragma unroll
            for (int i = 0; i < 8; i++) a[i] = As[k][tm + i];
            #pragma unroll
            for (int j = 0; j < 8; j++) bfr[j] = Bs[k][tn + j];
            #pragma unroll
            for (int i = 0; i < 8; i++)
                #pragma unroll
                for (int j = 0; j < 8; j++) acc[i][j] = fmaf(a[i], bfr[j], acc[i][j]);
        }
        __syncthreads();
    }

    #pragma unroll
    for (int i = 0; i < 8; i++) {
        size_t base = (size_t)(bm + tm + i) * N + bn + tn;
        #pragma unroll
        for (int j = 0; j < 8; j += 4) {
            float4 v = make_float4(acc[i][j], acc[i][j + 1], acc[i][j + 2], acc[i][j + 3]);
            if (addsrc) {
                float4 s = *(const float4*)(addsrc + base + j);
                v.x += s.x; v.y += s.y; v.z += s.z; v.w += s.w;
            }
            if (bias) {
                v.x += bias[bn + tn + j + 0]; v.y += bias[bn + tn + j + 1];
                v.z += bias[bn + tn + j + 2]; v.w += bias[bn + tn + j + 3];
            }
            *(float4*)(C + base + j) = v;
        }
    }
}

// ---------------- batched NT score GEMM: S[z] = scale * Q[z] @ K[z]^T ----------------
__global__ void __launch_bounds__(256) gemm_nt_scores_kernel(
    const float* __restrict__ Aall, const float* __restrict__ Ball,
    float* __restrict__ Call)
{
    const int K = D, N = N_CELLS;
    const float scale = 0.0625f;  // 256^-0.5
    int z = blockIdx.z;
    const float* A  = Aall + (size_t)z * N_DAY * D;
    const float* Bt = Ball + (size_t)z * N_CELLS * D;
    float* C        = Call + (size_t)z * N_DAY * (size_t)N_CELLS;

    __shared__ float As[BKK][BM + 4];
    __shared__ float Bs[BKK][BN + 4];
    int tid = threadIdx.x;
    int bm = blockIdx.y * BM;
    int bn = blockIdx.x * BN;
    int arow = tid >> 1, ak = (tid & 1) * 4;  // both operands: 128 rows x 8 k
    int tx = tid & 15, ty = tid >> 4;
    int tm = ty * 8, tn = tx * 8;

    float acc[8][8];
    #pragma unroll
    for (int i = 0; i < 8; i++)
        #pragma unroll
        for (int j = 0; j < 8; j++) acc[i][j] = 0.f;

    for (int k0 = 0; k0 < K; k0 += BKK) {
        float4 av = *(const float4*)(A  + (size_t)(bm + arow) * K + k0 + ak);
        float4 bv = *(const float4*)(Bt + (size_t)(bn + arow) * K + k0 + ak);
        As[ak + 0][arow] = av.x; As[ak + 1][arow] = av.y;
        As[ak + 2][arow] = av.z; As[ak + 3][arow] = av.w;
        Bs[ak + 0][arow] = bv.x; Bs[ak + 1][arow] = bv.y;
        Bs[ak + 2][arow] = bv.z; Bs[ak + 3][arow] = bv.w;
        __syncthreads();
        #pragma unroll
        for (int k = 0; k < BKK; k++) {
            float a[8], bfr[8];
            #pragma unroll
            for (int i = 0; i < 8; i++) a[i] = As[k][tm + i];
            #pragma unroll
            for (int j = 0; j < 8; j++) bfr[j] = Bs[k][tn + j];
            #pragma unroll
            for (int i = 0; i < 8; i++)
                #pragma unroll
                for (int j = 0; j < 8; j++) acc[i][j] = fmaf(a[i], bfr[j], acc[i][j]);
        }
        __syncthreads();
    }

    #pragma unroll
    for (int i = 0; i < 8; i++) {
        size_t base = (size_t)(bm + tm + i) * N_CELLS + bn + tn;
        #pragma unroll
        for (int j = 0; j < 8; j += 4) {
            float4 v = make_float4(acc[i][j] * scale, acc[i][j + 1] * scale,
                                   acc[i][j + 2] * scale, acc[i][j + 3] * scale);
            *(float4*)(C + base + j) = v;
        }
    }
}

// ---------------- top-32 + softmax per query row ----------------
__global__ void __launch_bounds__(256) topk_softmax_kernel(
    const float* __restrict__ scores, float* __restrict__ attn,
    float* __restrict__ idxo)
{
    __shared__ float srow[N_CELLS];
    __shared__ float swv[8];
    __shared__ int   swi[8];
    __shared__ float vals[TOPK];
    __shared__ int   inds[TOPK];

    size_t row = blockIdx.x;
    const float* sp = scores + row * (size_t)N_CELLS;
    int tid = threadIdx.x;

    for (int i = tid * 4; i < N_CELLS; i += 256 * 4)
        *(float4*)&srow[i] = *(const float4*)(sp + i);
    __syncthreads();

    for (int it = 0; it < TOPK; it++) {
        float v = -INFINITY; int id = 1 << 30;
        for (int j = tid; j < N_CELLS; j += 256) {
            float x = srow[j];
            if (x > v) { v = x; id = j; }   // j strictly increasing per-thread: first (lowest) index kept on tie
        }
        #pragma unroll
        for (int off = 16; off; off >>= 1) {
            float ov = __shfl_down_sync(0xffffffff, v, off);
            int   oi = __shfl_down_sync(0xffffffff, id, off);
            if (ov > v || (ov == v && oi < id)) { v = ov; id = oi; }
        }
        if ((tid & 31) == 0) { swv[tid >> 5] = v; swi[tid >> 5] = id; }
        __syncthreads();
        if (tid == 0) {
            float bv = swv[0]; int bi = swi[0];
            #pragma unroll
            for (int w = 1; w < 8; w++)
                if (swv[w] > bv || (swv[w] == bv && swi[w] < bi)) { bv = swv[w]; bi = swi[w]; }
            vals[it] = bv; inds[it] = bi;
            srow[bi] = -INFINITY;
        }
        __syncthreads();
    }

    if (tid < TOPK) {
        float m = vals[0];
        float e = expf(vals[tid] - m);
        float s = e;
        #pragma unroll
        for (int off = 16; off; off >>= 1) s += __shfl_xor_sync(0xffffffff, s, off);
        attn[row * TOPK + tid] = e / s;
        idxo[row * TOPK + tid] = (float)inds[tid];
    }
}

// ---------------- gather-weighted context: ctx[r,:] = sum_k w_k * V[b, idx_k, :] ----------------
__global__ void __launch_bounds__(256) context_kernel(
    const float* __restrict__ V, const float* __restrict__ attn,
    const float* __restrict__ idxf, float* __restrict__ ctx)
{
    __shared__ float w[TOPK];
    __shared__ int   id[TOPK];
    int row = blockIdx.x;
    int b = row >> 11;  // / N_DAY
    int tid = threadIdx.x;
    if (tid < TOPK) {
        w[tid]  = attn[(size_t)row * TOPK + tid];
        id[tid] = (int)idxf[(size_t)row * TOPK + tid];
    }
    __syncthreads();
    const float* Vb = V + (size_t)b * N_CELLS * D;
    float acc = 0.f;
    #pragma unroll 8
    for (int k = 0; k < TOPK; k++)
        acc = fmaf(w[k], Vb[(size_t)id[k] * D + tid], acc);
    ctx[(size_t)row * D + tid] = acc;
}

// ---------------- launch ----------------
extern "C" void kernel_launch(void* const* d_in, const int* in_sizes, int n_in,
                              void* d_out, int out_size)
{
    const float* micro = (const float*)d_in[0];
    const float* macro = (const float*)d_in[1];
    const float* mp_w  = (const float*)d_in[2];
    const float* mp_b  = (const float*)d_in[3];
    const float* wq    = (const float*)d_in[4];
    const float* wk    = (const float*)d_in[5];
    const float* wv    = (const float*)d_in[6];
    const float* op_w  = (const float*)d_in[7];
    const float* op_b  = (const float*)d_in[8];

    float* out  = (float*)d_out;
    float* attn = out + (size_t)ROWS_Q * D;                 // 2,097,152
    float* idxo = attn + (size_t)ROWS_Q * TOPK;             // +262,144

    float *p_xm, *p_q, *p_k, *p_v, *p_s, *p_c;
    cudaGetSymbolAddress((void**)&p_xm, g_xmicro);
    cudaGetSymbolAddress((void**)&p_q,  g_q);
    cudaGetSymbolAddress((void**)&p_k,  g_k);
    cudaGetSymbolAddress((void**)&p_v,  g_v);
    cudaGetSymbolAddress((void**)&p_s,  g_scores);
    cudaGetSymbolAddress((void**)&p_c,  g_ctx);

    // 1. x_micro = micro @ mp_w + mp_b
    micro_proj_kernel<<<ROWS_Q / 8, 256>>>(micro, mp_w, mp_b, p_xm);

    // 2. Q = x_micro @ wq ; K_full = macro @ wk ; V_full = macro @ wv
    gemm_nn_kernel<<<dim3(D / BN, ROWS_Q / BM), 256>>>(p_xm, wq, p_q, ROWS_Q, D, D, nullptr, nullptr);
    gemm_nn_kernel<<<dim3(D / BN, ROWS_M / BM), 256>>>(macro, wk, p_k, ROWS_M, D, D, nullptr, nullptr);
    gemm_nn_kernel<<<dim3(D / BN, ROWS_M / BM), 256>>>(macro, wv, p_v, ROWS_M, D, D, nullptr, nullptr);

    // 3. scores = scale * Q @ K^T  (batched)
    gemm_nt_scores_kernel<<<dim3(N_CELLS / BN, N_DAY / BM, BATCH), 256>>>(p_q, p_k, p_s);

    // 4. top-32 + softmax -> attn_weights, topk_idx (directly into d_out)
    topk_softmax_kernel<<<ROWS_Q, 256>>>(p_s, attn, idxo);

    // 5. context = sum_k w_k * V[idx_k]
    context_kernel<<<ROWS_Q, 256>>>(p_v, attn, idxo, p_c);

    // 6. x_conditioned = x_micro + context @ op_w + op_b
    gemm_nn_kernel<<<dim3(D / BN, ROWS_Q / BM), 256>>>(p_c, op_w, out, ROWS_Q, D, D, p_xm, op_b);

    (void)in_sizes; (void)n_in; (void)out_size;
}